// round 14
// baseline (speedup 1.0000x reference)
#include <cuda_runtime.h>
#include <cuda_fp16.h>

#define N_NODES 50000
#define N_EDGES 800000
#define HID 32
#define NLAYERS 4
#define SCAN_B 256
#define NBLK_SCAN ((N_NODES + SCAN_B - 1) / SCAN_B)   // 196
#define NB_N ((N_NODES + 255) / 256)                  // 196
#define NB_E ((N_EDGES + 255) / 256)                  // 3125
#define NODE_T 384
#define NB_NODE ((N_NODES + NODE_T - 1) / NODE_T)     // 131 (single wave)

// ---------------- device scratch (no runtime allocation allowed) ----------------
__device__ float g_h[N_NODES * HID];
__device__ float g_x[N_NODES * 2];
__device__ float g_A[N_NODES * HID];      // h @ W1[0:32] + b1
__device__ float g_B[N_NODES * HID];      // h @ W1[32:64]
__device__ float g_agg[N_NODES * HID];
__device__ float g_xacc[N_NODES * 2];
__device__ int   g_hist[N_NODES];
__device__ int   g_cur[N_NODES];
__device__ volatile unsigned g_flag[NBLK_SCAN];
__device__ int4  g_rce[N_EDGES];          // sorted (row, col, ea_bits, unused)

__device__ __forceinline__ float silu(float x) {
    float h = 0.5f * x, t;
    asm("tanh.approx.f32 %0, %1;" : "=f"(t) : "f"(h));
    return fmaf(h, t, h);
}

__device__ __forceinline__ float2 ffma2(float2 a, float2 b, float2 c) {
    float2 d;
    asm("fma.rn.f32x2 %0, %1, %2, %3;"
        : "=l"(reinterpret_cast<unsigned long long&>(d))
        : "l"(reinterpret_cast<unsigned long long&>(a)),
          "l"(reinterpret_cast<unsigned long long&>(b)),
          "l"(reinterpret_cast<unsigned long long&>(c)));
    return d;
}

// mma m16n8k16 f16 x f16 -> f32
__device__ __forceinline__ void mma16816(float4& d,
    unsigned a0, unsigned a1, unsigned a2, unsigned a3,
    unsigned b0, unsigned b1)
{
    asm volatile(
        "mma.sync.aligned.m16n8k16.row.col.f32.f16.f16.f32 "
        "{%0,%1,%2,%3}, {%4,%5,%6,%7}, {%8,%9}, {%0,%1,%2,%3};"
        : "+f"(d.x), "+f"(d.y), "+f"(d.z), "+f"(d.w)
        : "r"(a0), "r"(a1), "r"(a2), "r"(a3), "r"(b0), "r"(b1));
}

__device__ __forceinline__ void ldsm4(unsigned& r0, unsigned& r1, unsigned& r2, unsigned& r3,
                                      unsigned addr)
{
    asm volatile("ldmatrix.sync.aligned.m8n8.x4.shared.b16 {%0,%1,%2,%3}, [%4];"
        : "=r"(r0), "=r"(r1), "=r"(r2), "=r"(r3) : "r"(addr));
}

__device__ __forceinline__ unsigned packh2(float lo, float hi) {
    __half2 h = __floats2half2_rn(lo, hi);
    return *reinterpret_cast<unsigned*>(&h);
}

template<int IN, bool DOSILU, bool HASBIAS>
__device__ __forceinline__ void matvec32(const float* __restrict__ in,
                                         const float* __restrict__ Wsh,
                                         const float* __restrict__ bsh,
                                         float* __restrict__ out)
{
    float2 acc[16];
#pragma unroll
    for (int j = 0; j < 16; j++)
        acc[j] = HASBIAS ? reinterpret_cast<const float2*>(bsh)[j] : make_float2(0.f, 0.f);
#pragma unroll
    for (int i = 0; i < IN; i++) {
        float v = in[i];
        float2 vv = make_float2(v, v);
        const float4* w = reinterpret_cast<const float4*>(Wsh + i * 32);
#pragma unroll
        for (int j = 0; j < 8; j++) {
            float4 w4 = w[j];
            acc[2 * j]     = ffma2(vv, make_float2(w4.x, w4.y), acc[2 * j]);
            acc[2 * j + 1] = ffma2(vv, make_float2(w4.z, w4.w), acc[2 * j + 1]);
        }
    }
#pragma unroll
    for (int j = 0; j < 16; j++) {
        float a = acc[j].x, b = acc[j].y;
        if (DOSILU) { a = silu(a); b = silu(b); }
        out[2 * j] = a; out[2 * j + 1] = b;
    }
}

__device__ __forceinline__ void store32(float* dst, const float* v) {
#pragma unroll
    for (int j = 0; j < 8; j++)
        reinterpret_cast<float4*>(dst)[j] =
            make_float4(v[4 * j], v[4 * j + 1], v[4 * j + 2], v[4 * j + 3]);
}

// ---------------- launch 0: node init (+ layer-0 A/B) fused with edge histogram ----------------
__global__ __launch_bounds__(256) void k_inithist(
    const float* __restrict__ data, const float* __restrict__ pos,
    const float* __restrict__ tptr,
    const float* __restrict__ w, const float* __restrict__ b,
    const float* __restrict__ ew1, const float* __restrict__ eb1,
    const int* __restrict__ row)
{
    if (blockIdx.x >= NB_N) {
        int e = (blockIdx.x - NB_N) * 256 + threadIdx.x;
        if (e < N_EDGES) atomicAdd(&g_hist[row[e]], 1);
        return;
    }
    __shared__ __align__(16) float sW[65 * 32];
    __shared__ __align__(16) float sE[64 * 32];
    __shared__ __align__(16) float sb[32], seb[32];
    int t = threadIdx.x;
    for (int i = t; i < 65 * 32; i += blockDim.x) sW[i] = w[i];
    for (int i = t; i < 64 * 32; i += blockDim.x) sE[i] = ew1[i];
    if (t < 32) { sb[t] = b[t]; seb[t] = eb1[t]; }
    __syncthreads();

    int n = blockIdx.x * blockDim.x + t;
    if (n >= N_NODES) return;

    float in[65];
    in[0] = tptr[0];
    const float4* dv = reinterpret_cast<const float4*>(data + n * 64);
#pragma unroll
    for (int i = 0; i < 16; i++) {
        float4 d = dv[i];
        in[1 + 4 * i + 0] = d.x; in[1 + 4 * i + 1] = d.y;
        in[1 + 4 * i + 2] = d.z; in[1 + 4 * i + 3] = d.w;
    }
    float hv[32];
    matvec32<65, false, true>(in, sW, sb, hv);
    store32(g_h + n * 32, hv);

    float a[32], bb[32];
    matvec32<32, false, true >(hv, sE,           seb, a);
    matvec32<32, false, false>(hv, sE + 32 * 32, seb, bb);
    store32(g_A + n * 32, a);
    store32(g_B + n * 32, bb);

    float4* aout = reinterpret_cast<float4*>(g_agg + n * 32);
#pragma unroll
    for (int j = 0; j < 8; j++) aout[j] = make_float4(0.f, 0.f, 0.f, 0.f);
    reinterpret_cast<float2*>(g_x)[n] = reinterpret_cast<const float2*>(pos)[n];
    reinterpret_cast<float2*>(g_xacc)[n] = make_float2(0.f, 0.f);
}

// ---------------- launch 1: single-pass exclusive scan (decoupled lookback) ----------------
__global__ __launch_bounds__(SCAN_B) void k_scan_lb()
{
    __shared__ int buf[SCAN_B];
    __shared__ int s_excl;
    int b = blockIdx.x, t = threadIdx.x;
    int i = b * SCAN_B + t;
    int v = (i < N_NODES) ? g_hist[i] : 0;
    buf[t] = v;
    __syncthreads();
#pragma unroll
    for (int d = 1; d < SCAN_B; d <<= 1) {
        int x = (t >= d) ? buf[t - d] : 0;
        __syncthreads();
        buf[t] += x;
        __syncthreads();
    }
    int incl = buf[t];
    int total = buf[SCAN_B - 1];
    if (t == 0) {
        if (b == 0) { g_flag[0] = (2u << 30) | (unsigned)total; s_excl = 0; }
        else        { g_flag[b] = (1u << 30) | (unsigned)total; }
    }
    if (b > 0 && t < 32) {
        int excl = 0;
        int look = b - 1;
        while (true) {
            int idx = look - t;
            unsigned f;
            if (idx >= 0) { do { f = g_flag[idx]; } while ((f >> 30) == 0u); }
            else f = (2u << 30);
            unsigned pm = __ballot_sync(0xFFFFFFFFu, (f >> 30) == 2u);
            int firstp = __ffs(pm) - 1;
            int val = (int)(f & 0x3FFFFFFFu);
            int contrib = pm ? ((t <= firstp) ? val : 0) : val;
#pragma unroll
            for (int d = 16; d; d >>= 1) contrib += __shfl_xor_sync(0xFFFFFFFFu, contrib, d);
            excl += contrib;
            if (pm) break;
            look -= 32;
        }
        if (t == 0) {
            g_flag[b] = (2u << 30) | (unsigned)(excl + total);
            s_excl = excl;
        }
    }
    __syncthreads();
    if (i < N_NODES) g_cur[i] = s_excl + incl - v;
}

// ---------------- launch 2: scatter edges into row-sorted order (one 16B store) ----------------
__global__ __launch_bounds__(256) void k_scatter(
    const int* __restrict__ row, const int* __restrict__ col,
    const float* __restrict__ ea)
{
    int e = blockIdx.x * blockDim.x + threadIdx.x;
    if (e >= N_EDGES) return;
    int r = row[e];
    int p = atomicAdd(&g_cur[r], 1);
    g_rce[p] = make_int4(r, col[e], __float_as_int(ea[e]), 0);
}

// ---------------- edge kernel: pipelined; bv holds the full pre-activation ----------------
#define WPB 4
#define EDGE_BLOCKS 592          // 148 SM x 4 resident blocks
#define TS16 40                  // half-stride per edge row (80B: conflict-free)
__global__ __launch_bounds__(128, 4) void k_edge(
    const float* __restrict__ ew1,
    const float* __restrict__ ew2, const float* __restrict__ eb2,
    const float* __restrict__ cw1, const float* __restrict__ cb1,
    const float* __restrict__ cw2)
{
    __shared__ __align__(16) __half  sT[WPB][32 * TS16];  // [edge][feature] fp16
    __shared__ __align__(16) float4  sRCE[WPB][2][32];    // double-buffered edge metadata
    __shared__ __align__(16) uint2   sFrag[16][32];       // [pair][lane]; p<8: W2, p>=8: C1

    int t = threadIdx.x, warp = t >> 5, l = t & 31;
    int g = l >> 2, tg = l & 3;
    __half* T = sT[warp];
    unsigned Tbase = (unsigned)__cvta_generic_to_shared(T);

    if (t < 32) {
#pragma unroll
        for (int kt = 0; kt < 2; kt++)
#pragma unroll
            for (int nt = 0; nt < 4; nt++) {
                int k0 = kt * 16 + 2 * tg, n = nt * 8 + g;
                sFrag[kt * 4 + nt][t] = make_uint2(
                    packh2(__ldg(&ew2[k0 * 32 + n]),       __ldg(&ew2[(k0 + 1) * 32 + n])),
                    packh2(__ldg(&ew2[(k0 + 8) * 32 + n]), __ldg(&ew2[(k0 + 9) * 32 + n])));
                sFrag[8 + kt * 4 + nt][t] = make_uint2(
                    packh2(__ldg(&cw1[k0 * 32 + n]),       __ldg(&cw1[(k0 + 1) * 32 + n])),
                    packh2(__ldg(&cw1[(k0 + 8) * 32 + n]), __ldg(&cw1[(k0 + 9) * 32 + n])));
            }
    }
    float2 ebv[4], cbv[4], cwv[4];
#pragma unroll
    for (int nt = 0; nt < 4; nt++) {
        int c = nt * 8 + 2 * tg;
        ebv[nt] = make_float2(__ldg(&eb2[c]), __ldg(&eb2[c + 1]));
        cbv[nt] = make_float2(__ldg(&cb1[c]), __ldg(&cb1[c + 1]));
        cwv[nt] = make_float2(__ldg(&cw2[c]), __ldg(&cw2[c + 1]));
    }
    float wrl = __ldg(&ew1[64 * 32 + l]), wel = __ldg(&ew1[65 * 32 + l]);
    __syncthreads();

    int lrow = (l & 7) + 8 * ((l >> 3) & 1);
    int lcolh = 8 * (l >> 4);

    const int NT = N_EDGES / 32;
    const int NW = EDGE_BLOCKS * WPB;
    const int tile0 = blockIdx.x * WPB + warp;   // < NT always

    // carried state for the tile being consumed
    int rcur; float dxc, dyc; unsigned mbc, tmc;
    float bv[32];                                // full pre-activation per edge
    int buf = 0;

    // ---- prologue: prefetch tile0 (A dedup at segment heads; rad/ea folded in) ----
    {
        int4 rce = g_rce[tile0 * 32 + l];
        float eav = __int_as_float(rce.z);
        float2 xr = reinterpret_cast<const float2*>(g_x)[rce.x];
        float2 xc = reinterpret_cast<const float2*>(g_x)[rce.y];
        dxc = xr.x - xc.x; dyc = xr.y - xc.y;
        float radial = dxc * dxc + dyc * dyc;
        rcur = rce.x;
        int rp = __shfl_up_sync(0xFFFFFFFFu, rce.x, 1);
        bool head = (l == 0) || (rce.x != rp);
        mbc = __ballot_sync(0xFFFFFFFFu, head);
        tmc = (mbc >> 1) | 0x80000000u;
        sRCE[warp][0][l] = make_float4(__int_as_float(rce.x), __int_as_float(rce.y), radial, eav);
        __syncwarp();
        float aval = 0.f;
#pragma unroll
        for (int k = 0; k < 32; k++) {
            float4 q = sRCE[warp][0][k];
            if ((mbc >> k) & 1u) aval = __ldg(&g_A[__float_as_int(q.x) * 32 + l]);
            bv[k] = aval + __ldg(&g_B[__float_as_int(q.y) * 32 + l])
                  + q.z * wrl + q.w * wel;
        }
    }

    for (int tile = tile0; tile < NT; tile += NW) {
        int nb = buf ^ 1;
        int tn = tile + NW;
        int tcl = (tn < NT) ? tn : tile;         // clamped prefetch target

        // ---- consume: T[k][l] = silu(bv[k]) — no shared reads ----
#pragma unroll
        for (int k = 0; k < 32; k++)
            T[k * TS16 + l] = __float2half(silu(bv[k]));
        __syncwarp();

        // ---- P1: next tile edge data + masks + sRCE[nb] ----
        int rn2; float dx2, dy2; unsigned mb2, tm2;
        {
            int4 rce2 = g_rce[tcl * 32 + l];
            float eav2 = __int_as_float(rce2.z);
            float2 xr2 = reinterpret_cast<const float2*>(g_x)[rce2.x];
            float2 xc2 = reinterpret_cast<const float2*>(g_x)[rce2.y];
            dx2 = xr2.x - xc2.x; dy2 = xr2.y - xc2.y;
            float radial2 = dx2 * dx2 + dy2 * dy2;
            rn2 = rce2.x;
            int rp2 = __shfl_up_sync(0xFFFFFFFFu, rce2.x, 1);
            bool head2 = (l == 0) || (rce2.x != rp2);
            mb2 = __ballot_sync(0xFFFFFFFFu, head2);
            tm2 = (mb2 >> 1) | 0x80000000u;
            sRCE[warp][nb][l] = make_float4(__int_as_float(rce2.x), __int_as_float(rce2.y),
                                            radial2, eav2);
        }
        __syncwarp();

        // ---- GEMM1: m = silu(t1 @ W2 + b2) ----
#pragma unroll
        for (int mt = 0; mt < 2; mt++) {
            unsigned A0[4], A1[4];
            ldsm4(A0[0], A0[1], A0[2], A0[3],
                  Tbase + (unsigned)(((mt * 16 + lrow) * TS16 + lcolh) * 2));
            ldsm4(A1[0], A1[1], A1[2], A1[3],
                  Tbase + (unsigned)(((mt * 16 + lrow) * TS16 + 16 + lcolh) * 2));
            float4 D[4];
#pragma unroll
            for (int nt = 0; nt < 4; nt++)
                D[nt] = make_float4(ebv[nt].x, ebv[nt].y, ebv[nt].x, ebv[nt].y);
#pragma unroll
            for (int nt = 0; nt < 4; nt++) {
                uint2 p0 = sFrag[nt][l];
                uint2 p1 = sFrag[4 + nt][l];
                mma16816(D[nt], A0[0], A0[1], A0[2], A0[3], p0.x, p0.y);
                mma16816(D[nt], A1[0], A1[1], A1[2], A1[3], p1.x, p1.y);
            }
#pragma unroll
            for (int nt = 0; nt < 4; nt++) {
                unsigned lo = packh2(silu(D[nt].x), silu(D[nt].y));
                unsigned hi = packh2(silu(D[nt].z), silu(D[nt].w));
                *reinterpret_cast<unsigned*>(&T[(mt * 16 + g) * TS16 + nt * 8 + 2 * tg])     = lo;
                *reinterpret_cast<unsigned*>(&T[(mt * 16 + g + 8) * TS16 + nt * 8 + 2 * tg]) = hi;
            }
        }
        __syncwarp();

        // ---- sweep: lane = feature l, segment sums of m over sorted edges ----
        {
            float a = 0.f;
#pragma unroll
            for (int k = 0; k < 32; k++) {
                a += __half2float(T[k * TS16 + l]);
                if ((tmc >> k) & 1u) {
                    int rowk = __float_as_int(sRCE[warp][buf][k].x);
                    atomicAdd(&g_agg[rowk * 32 + l], a);
                    a = 0.f;
                }
            }
        }

        // ---- P2: next-tile pre-activation into registers (A dedup at heads) ----
        {
            float aval = 0.f;
#pragma unroll
            for (int k = 0; k < 32; k++) {
                float4 q = sRCE[warp][nb][k];
                if ((mb2 >> k) & 1u) aval = __ldg(&g_A[__float_as_int(q.x) * 32 + l]);
                bv[k] = aval + __ldg(&g_B[__float_as_int(q.y) * 32 + l])
                      + q.z * wrl + q.w * wel;
            }
        }

        // ---- GEMM2: q = silu(m @ C1 + cb1) * cw2; phi in regs ----
        float P[4] = {0.f, 0.f, 0.f, 0.f};
#pragma unroll
        for (int mt = 0; mt < 2; mt++) {
            unsigned A0[4], A1[4];
            ldsm4(A0[0], A0[1], A0[2], A0[3],
                  Tbase + (unsigned)(((mt * 16 + lrow) * TS16 + lcolh) * 2));
            ldsm4(A1[0], A1[1], A1[2], A1[3],
                  Tbase + (unsigned)(((mt * 16 + lrow) * TS16 + 16 + lcolh) * 2));
            float4 D[4];
#pragma unroll
            for (int nt = 0; nt < 4; nt++)
                D[nt] = make_float4(cbv[nt].x, cbv[nt].y, cbv[nt].x, cbv[nt].y);
#pragma unroll
            for (int nt = 0; nt < 4; nt++) {
                uint2 p0 = sFrag[8 + nt][l];
                uint2 p1 = sFrag[12 + nt][l];
                mma16816(D[nt], A0[0], A0[1], A0[2], A0[3], p0.x, p0.y);
                mma16816(D[nt], A1[0], A1[1], A1[2], A1[3], p1.x, p1.y);
            }
#pragma unroll
            for (int nt = 0; nt < 4; nt++) {
                P[mt * 2 + 0] += silu(D[nt].x) * cwv[nt].x + silu(D[nt].y) * cwv[nt].y;
                P[mt * 2 + 1] += silu(D[nt].z) * cwv[nt].x + silu(D[nt].w) * cwv[nt].y;
            }
        }
        __syncwarp();                            // last T reads done (safe for next consume)
#pragma unroll
        for (int d = 1; d < 4; d <<= 1) {
#pragma unroll
            for (int i = 0; i < 4; i++) P[i] += __shfl_xor_sync(0xFFFFFFFFu, P[i], d);
        }
        int src = (l & 7) * 4;
        float v0 = __shfl_sync(0xFFFFFFFFu, P[0], src);
        float v1 = __shfl_sync(0xFFFFFFFFu, P[1], src);
        float v2 = __shfl_sync(0xFFFFFFFFu, P[2], src);
        float v3 = __shfl_sync(0xFFFFFFFFu, P[3], src);
        int sel = l >> 3;
        float phi = (sel == 0) ? v0 : (sel == 1) ? v1 : (sel == 2) ? v2 : v3;

        // ---- coord: segmented inclusive scan, tails emit atomics ----
        {
            float vx = dxc * phi, vy = dyc * phi;
            unsigned lem = 0xFFFFFFFFu >> (31 - l);
            int start = 31 - __clz(mbc & lem);
#pragma unroll
            for (int d = 1; d < 32; d <<= 1) {
                float tx = __shfl_up_sync(0xFFFFFFFFu, vx, d);
                float ty = __shfl_up_sync(0xFFFFFFFFu, vy, d);
                if (l - d >= start) { vx += tx; vy += ty; }
            }
            if ((tmc >> l) & 1u) {
                atomicAdd(&g_xacc[2 * rcur + 0], vx);
                atomicAdd(&g_xacc[2 * rcur + 1], vy);
            }
        }

        // rotate pipeline state
        rcur = rn2; dxc = dx2; dyc = dy2; mbc = mb2; tmc = tm2; buf = nb;
    }
}

// ---------------- per layer: coord update + node MLP; NEXT computes next A/B;
// ---------------- OUT fuses the final projection + replay-state resets ----------------
template<bool NEXT, bool OUT>
__global__ __launch_bounds__(NODE_T) void k_node(
    const float* __restrict__ nw1, const float* __restrict__ nb1,
    const float* __restrict__ nw2, const float* __restrict__ nb2,
    const float* __restrict__ ew1n, const float* __restrict__ eb1n,
    const float* __restrict__ ow, const float* __restrict__ ob,
    float* __restrict__ out)
{
    __shared__ __align__(16) float sW1[64 * 32];
    __shared__ __align__(16) float sW2[32 * 32];
    __shared__ __align__(16) float sE[64 * 32];
    __shared__ __align__(16) float sb1[32], sb2[32], seb[64];
    int t = threadIdx.x;
    for (int i = t; i < 64 * 32; i += blockDim.x) sW1[i] = nw1[i];
    for (int i = t; i < 32 * 32; i += blockDim.x) sW2[i] = nw2[i];
    if (NEXT) {
        for (int i = t; i < 64 * 32; i += blockDim.x) sE[i] = ew1n[i];
        if (t < 32) seb[t] = eb1n[t];
    }
    if (OUT) {
        for (int i = t; i < 32 * 64; i += blockDim.x) sE[i] = ow[i];
        if (t < 64) seb[t] = ob[t];
    }
    if (t < 32) { sb1[t] = nb1[t]; sb2[t] = nb2[t]; }
    __syncthreads();

    int n = blockIdx.x * blockDim.x + t;
    if (n >= N_NODES) return;

    float cnt = (float)max(g_hist[n], 1);
    if (OUT) {
        g_hist[n] = 0;
        if (blockIdx.x == 0 && t < NBLK_SCAN) g_flag[t] = 0;
    }
    float inv = __fdividef(1.0f, cnt);
    float2 xa = reinterpret_cast<float2*>(g_xacc)[n];
    if (!OUT) {
        float2 xv = reinterpret_cast<float2*>(g_x)[n];
        xv.x = fmaf(xa.x, inv, xv.x);
        xv.y = fmaf(xa.y, inv, xv.y);
        reinterpret_cast<float2*>(g_x)[n] = xv;
        reinterpret_cast<float2*>(g_xacc)[n] = make_float2(0.f, 0.f);
    }

    float cat[64];
    float4* hio = reinterpret_cast<float4*>(g_h + n * 32);
    float4* agp = reinterpret_cast<float4*>(g_agg + n * 32);
#pragma unroll
    for (int i = 0; i < 8; i++) {
        float4 h4 = hio[i], a4 = agp[i];
        cat[4 * i + 0] = h4.x; cat[4 * i + 1] = h4.y; cat[4 * i + 2] = h4.z; cat[4 * i + 3] = h4.w;
        cat[32 + 4 * i + 0] = a4.x; cat[32 + 4 * i + 1] = a4.y;
        cat[32 + 4 * i + 2] = a4.z; cat[32 + 4 * i + 3] = a4.w;
        agp[i] = make_float4(0.f, 0.f, 0.f, 0.f);
    }
    float u[32];
    matvec32<64, true, true>(cat, sW1, sb1, u);
    float upd[32];
    matvec32<32, false, true>(u, sW2, sb2, upd);
    float hn[32];
#pragma unroll
    for (int i = 0; i < 32; i++) hn[i] = cat[i] + upd[i];

    if (NEXT) {
        store32(g_h + n * 32, hn);
        float a[32], bb[32];
        matvec32<32, false, true >(hn, sE,           seb, a);
        matvec32<32, false, false>(hn, sE + 32 * 32, seb, bb);
        store32(g_A + n * 32, a);
        store32(g_B + n * 32, bb);
    }
    if (OUT) {
        float2 acc[32];
#pragma unroll
        for (int j = 0; j < 32; j++) acc[j] = reinterpret_cast<const float2*>(seb)[j];
#pragma unroll
        for (int i = 0; i < 32; i++) {
            float2 vv = make_float2(hn[i], hn[i]);
            const float4* wr = reinterpret_cast<const float4*>(sE + i * 64);
#pragma unroll
            for (int j = 0; j < 16; j++) {
                float4 w4 = wr[j];
                acc[2 * j]     = ffma2(vv, make_float2(w4.x, w4.y), acc[2 * j]);
                acc[2 * j + 1] = ffma2(vv, make_float2(w4.z, w4.w), acc[2 * j + 1]);
            }
        }
        float2* op = reinterpret_cast<float2*>(out + n * 64);
#pragma unroll
        for (int j = 0; j < 32; j++) op[j] = acc[j];
    }
}

// ---------------- host launcher ----------------
extern "C" void kernel_launch(void* const* d_in, const int* in_sizes, int n_in,
                              void* d_out, int out_size)
{
    const float* data      = (const float*)d_in[0];
    const float* pos       = (const float*)d_in[1];
    const float* ea        = (const float*)d_in[2];
    const float* tptr      = (const float*)d_in[3];
    const int*   row       = (const int*)d_in[4];
    const int*   col       = (const int*)d_in[5];
    const float* emb_in_w  = (const float*)d_in[6];
    const float* emb_in_b  = (const float*)d_in[7];
    const float* emb_out_w = (const float*)d_in[8];
    const float* emb_out_b = (const float*)d_in[9];
    const float* edge_w1   = (const float*)d_in[10];
    const float* edge_b1   = (const float*)d_in[11];
    const float* edge_w2   = (const float*)d_in[12];
    const float* edge_b2   = (const float*)d_in[13];
    const float* node_w1   = (const float*)d_in[14];
    const float* node_b1   = (const float*)d_in[15];
    const float* node_w2   = (const float*)d_in[16];
    const float* node_b2   = (const float*)d_in[17];
    const float* coord_w1  = (const float*)d_in[18];
    const float* coord_b1  = (const float*)d_in[19];
    const float* coord_w2  = (const float*)d_in[20];

    k_inithist<<<NB_N + NB_E, 256>>>(data, pos, tptr, emb_in_w, emb_in_b,
                                     edge_w1, edge_b1, row);
    k_scan_lb<<<NBLK_SCAN, SCAN_B>>>();
    k_scatter<<<NB_E, 256>>>(row, col, ea);

    for (int l = 0; l < NLAYERS; l++) {
        k_edge<<<EDGE_BLOCKS, 32 * WPB>>>(edge_w1 + l * 66 * 32,
                              edge_w2 + l * 1024, edge_b2 + l * 32,
                              coord_w1 + l * 1024, coord_b1 + l * 32,
                              coord_w2 + l * 32);
        if (l < NLAYERS - 1)
            k_node<true, false><<<NB_NODE, NODE_T>>>(node_w1 + l * 2048, node_b1 + l * 32,
                                        node_w2 + l * 1024, node_b2 + l * 32,
                                        edge_w1 + (l + 1) * 66 * 32, edge_b1 + (l + 1) * 32,
                                        nullptr, nullptr, nullptr);
        else
            k_node<false, true><<<NB_NODE, NODE_T>>>(node_w1 + l * 2048, node_b1 + l * 32,
                                         node_w2 + l * 1024, node_b2 + l * 32,
                                         nullptr, nullptr,
                                         emb_out_w, emb_out_b, (float*)d_out);
    }
}

// round 15
// speedup vs baseline: 1.2636x; 1.2636x over previous
#include <cuda_runtime.h>
#include <cuda_fp16.h>

#define N_NODES 50000
#define N_EDGES 800000
#define HID 32
#define NLAYERS 4
#define SCAN_B 256
#define NBLK_SCAN ((N_NODES + SCAN_B - 1) / SCAN_B)   // 196
#define NB_N ((N_NODES + 255) / 256)                  // 196
#define NB_E ((N_EDGES + 255) / 256)                  // 3125
#define NODE_T 384
#define NB_NODE ((N_NODES + NODE_T - 1) / NODE_T)     // 131 (single wave)

// ---------------- device scratch (no runtime allocation allowed) ----------------
__device__ float g_h[N_NODES * HID];
__device__ float g_x[N_NODES * 2];
__device__ float g_A[N_NODES * HID];      // h @ W1[0:32] + b1
__device__ float g_B[N_NODES * HID];      // h @ W1[32:64]
__device__ float g_agg[N_NODES * HID];
__device__ float g_xacc[N_NODES * 2];
__device__ int   g_hist[N_NODES];
__device__ int   g_cur[N_NODES];
__device__ volatile unsigned g_flag[NBLK_SCAN];
__device__ int4  g_rce[N_EDGES];          // sorted (row, col, ea_bits, unused)

__device__ __forceinline__ float silu(float x) {
    float h = 0.5f * x, t;
    asm("tanh.approx.f32 %0, %1;" : "=f"(t) : "f"(h));
    return fmaf(h, t, h);
}

__device__ __forceinline__ float2 ffma2(float2 a, float2 b, float2 c) {
    float2 d;
    asm("fma.rn.f32x2 %0, %1, %2, %3;"
        : "=l"(reinterpret_cast<unsigned long long&>(d))
        : "l"(reinterpret_cast<unsigned long long&>(a)),
          "l"(reinterpret_cast<unsigned long long&>(b)),
          "l"(reinterpret_cast<unsigned long long&>(c)));
    return d;
}

// mma m16n8k16 f16 x f16 -> f32
__device__ __forceinline__ void mma16816(float4& d,
    unsigned a0, unsigned a1, unsigned a2, unsigned a3,
    unsigned b0, unsigned b1)
{
    asm volatile(
        "mma.sync.aligned.m16n8k16.row.col.f32.f16.f16.f32 "
        "{%0,%1,%2,%3}, {%4,%5,%6,%7}, {%8,%9}, {%0,%1,%2,%3};"
        : "+f"(d.x), "+f"(d.y), "+f"(d.z), "+f"(d.w)
        : "r"(a0), "r"(a1), "r"(a2), "r"(a3), "r"(b0), "r"(b1));
}

__device__ __forceinline__ void ldsm4(unsigned& r0, unsigned& r1, unsigned& r2, unsigned& r3,
                                      unsigned addr)
{
    asm volatile("ldmatrix.sync.aligned.m8n8.x4.shared.b16 {%0,%1,%2,%3}, [%4];"
        : "=r"(r0), "=r"(r1), "=r"(r2), "=r"(r3) : "r"(addr));
}

__device__ __forceinline__ unsigned packh2(float lo, float hi) {
    __half2 h = __floats2half2_rn(lo, hi);
    return *reinterpret_cast<unsigned*>(&h);
}

template<int IN, bool DOSILU, bool HASBIAS>
__device__ __forceinline__ void matvec32(const float* __restrict__ in,
                                         const float* __restrict__ Wsh,
                                         const float* __restrict__ bsh,
                                         float* __restrict__ out)
{
    float2 acc[16];
#pragma unroll
    for (int j = 0; j < 16; j++)
        acc[j] = HASBIAS ? reinterpret_cast<const float2*>(bsh)[j] : make_float2(0.f, 0.f);
#pragma unroll
    for (int i = 0; i < IN; i++) {
        float v = in[i];
        float2 vv = make_float2(v, v);
        const float4* w = reinterpret_cast<const float4*>(Wsh + i * 32);
#pragma unroll
        for (int j = 0; j < 8; j++) {
            float4 w4 = w[j];
            acc[2 * j]     = ffma2(vv, make_float2(w4.x, w4.y), acc[2 * j]);
            acc[2 * j + 1] = ffma2(vv, make_float2(w4.z, w4.w), acc[2 * j + 1]);
        }
    }
#pragma unroll
    for (int j = 0; j < 16; j++) {
        float a = acc[j].x, b = acc[j].y;
        if (DOSILU) { a = silu(a); b = silu(b); }
        out[2 * j] = a; out[2 * j + 1] = b;
    }
}

__device__ __forceinline__ void store32(float* dst, const float* v) {
#pragma unroll
    for (int j = 0; j < 8; j++)
        reinterpret_cast<float4*>(dst)[j] =
            make_float4(v[4 * j], v[4 * j + 1], v[4 * j + 2], v[4 * j + 3]);
}

// ---------------- launch 0: node init (+ layer-0 A/B) fused with edge histogram ----------------
__global__ __launch_bounds__(256) void k_inithist(
    const float* __restrict__ data, const float* __restrict__ pos,
    const float* __restrict__ tptr,
    const float* __restrict__ w, const float* __restrict__ b,
    const float* __restrict__ ew1, const float* __restrict__ eb1,
    const int* __restrict__ row)
{
    if (blockIdx.x >= NB_N) {
        int e = (blockIdx.x - NB_N) * 256 + threadIdx.x;
        if (e < N_EDGES) atomicAdd(&g_hist[row[e]], 1);
        return;
    }
    __shared__ __align__(16) float sW[65 * 32];
    __shared__ __align__(16) float sE[64 * 32];
    __shared__ __align__(16) float sb[32], seb[32];
    int t = threadIdx.x;
    for (int i = t; i < 65 * 32; i += blockDim.x) sW[i] = w[i];
    for (int i = t; i < 64 * 32; i += blockDim.x) sE[i] = ew1[i];
    if (t < 32) { sb[t] = b[t]; seb[t] = eb1[t]; }
    __syncthreads();

    int n = blockIdx.x * blockDim.x + t;
    if (n >= N_NODES) return;

    float in[65];
    in[0] = tptr[0];
    const float4* dv = reinterpret_cast<const float4*>(data + n * 64);
#pragma unroll
    for (int i = 0; i < 16; i++) {
        float4 d = dv[i];
        in[1 + 4 * i + 0] = d.x; in[1 + 4 * i + 1] = d.y;
        in[1 + 4 * i + 2] = d.z; in[1 + 4 * i + 3] = d.w;
    }
    float hv[32];
    matvec32<65, false, true>(in, sW, sb, hv);
    store32(g_h + n * 32, hv);

    float a[32], bb[32];
    matvec32<32, false, true >(hv, sE,           seb, a);
    matvec32<32, false, false>(hv, sE + 32 * 32, seb, bb);
    store32(g_A + n * 32, a);
    store32(g_B + n * 32, bb);

    float4* aout = reinterpret_cast<float4*>(g_agg + n * 32);
#pragma unroll
    for (int j = 0; j < 8; j++) aout[j] = make_float4(0.f, 0.f, 0.f, 0.f);
    reinterpret_cast<float2*>(g_x)[n] = reinterpret_cast<const float2*>(pos)[n];
    reinterpret_cast<float2*>(g_xacc)[n] = make_float2(0.f, 0.f);
}

// ---------------- launch 1: single-pass exclusive scan (decoupled lookback) ----------------
__global__ __launch_bounds__(SCAN_B) void k_scan_lb()
{
    __shared__ int buf[SCAN_B];
    __shared__ int s_excl;
    int b = blockIdx.x, t = threadIdx.x;
    int i = b * SCAN_B + t;
    int v = (i < N_NODES) ? g_hist[i] : 0;
    buf[t] = v;
    __syncthreads();
#pragma unroll
    for (int d = 1; d < SCAN_B; d <<= 1) {
        int x = (t >= d) ? buf[t - d] : 0;
        __syncthreads();
        buf[t] += x;
        __syncthreads();
    }
    int incl = buf[t];
    int total = buf[SCAN_B - 1];
    if (t == 0) {
        if (b == 0) { g_flag[0] = (2u << 30) | (unsigned)total; s_excl = 0; }
        else        { g_flag[b] = (1u << 30) | (unsigned)total; }
    }
    if (b > 0 && t < 32) {
        int excl = 0;
        int look = b - 1;
        while (true) {
            int idx = look - t;
            unsigned f;
            if (idx >= 0) { do { f = g_flag[idx]; } while ((f >> 30) == 0u); }
            else f = (2u << 30);
            unsigned pm = __ballot_sync(0xFFFFFFFFu, (f >> 30) == 2u);
            int firstp = __ffs(pm) - 1;
            int val = (int)(f & 0x3FFFFFFFu);
            int contrib = pm ? ((t <= firstp) ? val : 0) : val;
#pragma unroll
            for (int d = 16; d; d >>= 1) contrib += __shfl_xor_sync(0xFFFFFFFFu, contrib, d);
            excl += contrib;
            if (pm) break;
            look -= 32;
        }
        if (t == 0) {
            g_flag[b] = (2u << 30) | (unsigned)(excl + total);
            s_excl = excl;
        }
    }
    __syncthreads();
    if (i < N_NODES) g_cur[i] = s_excl + incl - v;
}

// ---------------- launch 2: scatter edges into row-sorted order (one 16B store) ----------------
__global__ __launch_bounds__(256) void k_scatter(
    const int* __restrict__ row, const int* __restrict__ col,
    const float* __restrict__ ea)
{
    int e = blockIdx.x * blockDim.x + threadIdx.x;
    if (e >= N_EDGES) return;
    int r = row[e];
    int p = atomicAdd(&g_cur[r], 1);
    g_rce[p] = make_int4(r, col[e], __float_as_int(ea[e]), 0);
}

// ---------------- edge kernel: pipelined; bv = full pre-activation, independent loads ----------------
#define WPB 4
#define EDGE_BLOCKS 592          // 148 SM x 4 resident blocks
#define TS16 40                  // half-stride per edge row (80B: conflict-free)
__global__ __launch_bounds__(128, 4) void k_edge(
    const float* __restrict__ ew1,
    const float* __restrict__ ew2, const float* __restrict__ eb2,
    const float* __restrict__ cw1, const float* __restrict__ cb1,
    const float* __restrict__ cw2)
{
    __shared__ __align__(16) __half  sT[WPB][32 * TS16];  // [edge][feature] fp16
    __shared__ __align__(16) float4  sRCE[WPB][2][32];    // double-buffered edge metadata
    __shared__ __align__(16) uint2   sFrag[16][32];       // [pair][lane]; p<8: W2, p>=8: C1

    int t = threadIdx.x, warp = t >> 5, l = t & 31;
    int g = l >> 2, tg = l & 3;
    __half* T = sT[warp];
    unsigned Tbase = (unsigned)__cvta_generic_to_shared(T);

    if (t < 32) {
#pragma unroll
        for (int kt = 0; kt < 2; kt++)
#pragma unroll
            for (int nt = 0; nt < 4; nt++) {
                int k0 = kt * 16 + 2 * tg, n = nt * 8 + g;
                sFrag[kt * 4 + nt][t] = make_uint2(
                    packh2(__ldg(&ew2[k0 * 32 + n]),       __ldg(&ew2[(k0 + 1) * 32 + n])),
                    packh2(__ldg(&ew2[(k0 + 8) * 32 + n]), __ldg(&ew2[(k0 + 9) * 32 + n])));
                sFrag[8 + kt * 4 + nt][t] = make_uint2(
                    packh2(__ldg(&cw1[k0 * 32 + n]),       __ldg(&cw1[(k0 + 1) * 32 + n])),
                    packh2(__ldg(&cw1[(k0 + 8) * 32 + n]), __ldg(&cw1[(k0 + 9) * 32 + n])));
            }
    }
    float2 ebv[4], cbv[4], cwv[4];
#pragma unroll
    for (int nt = 0; nt < 4; nt++) {
        int c = nt * 8 + 2 * tg;
        ebv[nt] = make_float2(__ldg(&eb2[c]), __ldg(&eb2[c + 1]));
        cbv[nt] = make_float2(__ldg(&cb1[c]), __ldg(&cb1[c + 1]));
        cwv[nt] = make_float2(__ldg(&cw2[c]), __ldg(&cw2[c + 1]));
    }
    float wrl = __ldg(&ew1[64 * 32 + l]), wel = __ldg(&ew1[65 * 32 + l]);
    __syncthreads();

    int lrow = (l & 7) + 8 * ((l >> 3) & 1);
    int lcolh = 8 * (l >> 4);

    const int NT = N_EDGES / 32;
    const int NW = EDGE_BLOCKS * WPB;
    const int tile0 = blockIdx.x * WPB + warp;   // < NT always

    // carried state for the tile being consumed
    int rcur; float dxc, dyc; unsigned mbc, tmc;
    float bv[32];                                // full pre-activation per edge
    int buf = 0;

    // ---- prologue: prefetch tile0 (independent loads; rad/ea folded in) ----
    {
        int4 rce = g_rce[tile0 * 32 + l];
        float eav = __int_as_float(rce.z);
        float2 xr = reinterpret_cast<const float2*>(g_x)[rce.x];
        float2 xc = reinterpret_cast<const float2*>(g_x)[rce.y];
        dxc = xr.x - xc.x; dyc = xr.y - xc.y;
        float radial = dxc * dxc + dyc * dyc;
        rcur = rce.x;
        int rp = __shfl_up_sync(0xFFFFFFFFu, rce.x, 1);
        bool head = (l == 0) || (rce.x != rp);
        mbc = __ballot_sync(0xFFFFFFFFu, head);
        tmc = (mbc >> 1) | 0x80000000u;
        sRCE[warp][0][l] = make_float4(__int_as_float(rce.x), __int_as_float(rce.y), radial, eav);
        __syncwarp();
#pragma unroll
        for (int k = 0; k < 32; k++) {
            float4 q = sRCE[warp][0][k];
            bv[k] = __ldg(&g_A[__float_as_int(q.x) * 32 + l])
                  + __ldg(&g_B[__float_as_int(q.y) * 32 + l])
                  + q.z * wrl + q.w * wel;
        }
    }

    for (int tile = tile0; tile < NT; tile += NW) {
        int nb = buf ^ 1;
        int tn = tile + NW;
        int tcl = (tn < NT) ? tn : tile;         // clamped prefetch target

        // ---- consume: T[k][l] = silu(bv[k]) — no shared reads ----
#pragma unroll
        for (int k = 0; k < 32; k++)
            T[k * TS16 + l] = __float2half(silu(bv[k]));
        __syncwarp();

        // ---- P1: next tile edge data + masks + sRCE[nb] ----
        int rn2; float dx2, dy2; unsigned mb2, tm2;
        {
            int4 rce2 = g_rce[tcl * 32 + l];
            float eav2 = __int_as_float(rce2.z);
            float2 xr2 = reinterpret_cast<const float2*>(g_x)[rce2.x];
            float2 xc2 = reinterpret_cast<const float2*>(g_x)[rce2.y];
            dx2 = xr2.x - xc2.x; dy2 = xr2.y - xc2.y;
            float radial2 = dx2 * dx2 + dy2 * dy2;
            rn2 = rce2.x;
            int rp2 = __shfl_up_sync(0xFFFFFFFFu, rce2.x, 1);
            bool head2 = (l == 0) || (rce2.x != rp2);
            mb2 = __ballot_sync(0xFFFFFFFFu, head2);
            tm2 = (mb2 >> 1) | 0x80000000u;
            sRCE[warp][nb][l] = make_float4(__int_as_float(rce2.x), __int_as_float(rce2.y),
                                            radial2, eav2);
        }
        __syncwarp();

        // ---- GEMM1: m = silu(t1 @ W2 + b2) ----
#pragma unroll
        for (int mt = 0; mt < 2; mt++) {
            unsigned A0[4], A1[4];
            ldsm4(A0[0], A0[1], A0[2], A0[3],
                  Tbase + (unsigned)(((mt * 16 + lrow) * TS16 + lcolh) * 2));
            ldsm4(A1[0], A1[1], A1[2], A1[3],
                  Tbase + (unsigned)(((mt * 16 + lrow) * TS16 + 16 + lcolh) * 2));
            float4 D[4];
#pragma unroll
            for (int nt = 0; nt < 4; nt++)
                D[nt] = make_float4(ebv[nt].x, ebv[nt].y, ebv[nt].x, ebv[nt].y);
#pragma unroll
            for (int nt = 0; nt < 4; nt++) {
                uint2 p0 = sFrag[nt][l];
                uint2 p1 = sFrag[4 + nt][l];
                mma16816(D[nt], A0[0], A0[1], A0[2], A0[3], p0.x, p0.y);
                mma16816(D[nt], A1[0], A1[1], A1[2], A1[3], p1.x, p1.y);
            }
#pragma unroll
            for (int nt = 0; nt < 4; nt++) {
                unsigned lo = packh2(silu(D[nt].x), silu(D[nt].y));
                unsigned hi = packh2(silu(D[nt].z), silu(D[nt].w));
                *reinterpret_cast<unsigned*>(&T[(mt * 16 + g) * TS16 + nt * 8 + 2 * tg])     = lo;
                *reinterpret_cast<unsigned*>(&T[(mt * 16 + g + 8) * TS16 + nt * 8 + 2 * tg]) = hi;
            }
        }
        __syncwarp();

        // ---- sweep: lane = feature l, segment sums of m over sorted edges ----
        {
            float a = 0.f;
#pragma unroll
            for (int k = 0; k < 32; k++) {
                a += __half2float(T[k * TS16 + l]);
                if ((tmc >> k) & 1u) {
                    int rowk = __float_as_int(sRCE[warp][buf][k].x);
                    atomicAdd(&g_agg[rowk * 32 + l], a);
                    a = 0.f;
                }
            }
        }

        // ---- P2: next-tile pre-activation into registers (independent loads) ----
#pragma unroll
        for (int k = 0; k < 32; k++) {
            float4 q = sRCE[warp][nb][k];
            bv[k] = __ldg(&g_A[__float_as_int(q.x) * 32 + l])
                  + __ldg(&g_B[__float_as_int(q.y) * 32 + l])
                  + q.z * wrl + q.w * wel;
        }

        // ---- GEMM2: q = silu(m @ C1 + cb1) * cw2; phi in regs ----
        float P[4] = {0.f, 0.f, 0.f, 0.f};
#pragma unroll
        for (int mt = 0; mt < 2; mt++) {
            unsigned A0[4], A1[4];
            ldsm4(A0[0], A0[1], A0[2], A0[3],
                  Tbase + (unsigned)(((mt * 16 + lrow) * TS16 + lcolh) * 2));
            ldsm4(A1[0], A1[1], A1[2], A1[3],
                  Tbase + (unsigned)(((mt * 16 + lrow) * TS16 + 16 + lcolh) * 2));
            float4 D[4];
#pragma unroll
            for (int nt = 0; nt < 4; nt++)
                D[nt] = make_float4(cbv[nt].x, cbv[nt].y, cbv[nt].x, cbv[nt].y);
#pragma unroll
            for (int nt = 0; nt < 4; nt++) {
                uint2 p0 = sFrag[8 + nt][l];
                uint2 p1 = sFrag[12 + nt][l];
                mma16816(D[nt], A0[0], A0[1], A0[2], A0[3], p0.x, p0.y);
                mma16816(D[nt], A1[0], A1[1], A1[2], A1[3], p1.x, p1.y);
            }
#pragma unroll
            for (int nt = 0; nt < 4; nt++) {
                P[mt * 2 + 0] += silu(D[nt].x) * cwv[nt].x + silu(D[nt].y) * cwv[nt].y;
                P[mt * 2 + 1] += silu(D[nt].z) * cwv[nt].x + silu(D[nt].w) * cwv[nt].y;
            }
        }
        __syncwarp();                            // last T reads done (safe for next consume)
#pragma unroll
        for (int d = 1; d < 4; d <<= 1) {
#pragma unroll
            for (int i = 0; i < 4; i++) P[i] += __shfl_xor_sync(0xFFFFFFFFu, P[i], d);
        }
        int src = (l & 7) * 4;
        float v0 = __shfl_sync(0xFFFFFFFFu, P[0], src);
        float v1 = __shfl_sync(0xFFFFFFFFu, P[1], src);
        float v2 = __shfl_sync(0xFFFFFFFFu, P[2], src);
        float v3 = __shfl_sync(0xFFFFFFFFu, P[3], src);
        int sel = l >> 3;
        float phi = (sel == 0) ? v0 : (sel == 1) ? v1 : (sel == 2) ? v2 : v3;

        // ---- coord: segmented inclusive scan, tails emit atomics ----
        {
            float vx = dxc * phi, vy = dyc * phi;
            unsigned lem = 0xFFFFFFFFu >> (31 - l);
            int start = 31 - __clz(mbc & lem);
#pragma unroll
            for (int d = 1; d < 32; d <<= 1) {
                float tx = __shfl_up_sync(0xFFFFFFFFu, vx, d);
                float ty = __shfl_up_sync(0xFFFFFFFFu, vy, d);
                if (l - d >= start) { vx += tx; vy += ty; }
            }
            if ((tmc >> l) & 1u) {
                atomicAdd(&g_xacc[2 * rcur + 0], vx);
                atomicAdd(&g_xacc[2 * rcur + 1], vy);
            }
        }

        // rotate pipeline state
        rcur = rn2; dxc = dx2; dyc = dy2; mbc = mb2; tmc = tm2; buf = nb;
    }
}

// ---------------- per layer: coord update + node MLP; NEXT computes next A/B;
// ---------------- OUT fuses the final projection + replay-state resets ----------------
template<bool NEXT, bool OUT>
__global__ __launch_bounds__(NODE_T) void k_node(
    const float* __restrict__ nw1, const float* __restrict__ nb1,
    const float* __restrict__ nw2, const float* __restrict__ nb2,
    const float* __restrict__ ew1n, const float* __restrict__ eb1n,
    const float* __restrict__ ow, const float* __restrict__ ob,
    float* __restrict__ out)
{
    __shared__ __align__(16) float sW1[64 * 32];
    __shared__ __align__(16) float sW2[32 * 32];
    __shared__ __align__(16) float sE[64 * 32];
    __shared__ __align__(16) float sb1[32], sb2[32], seb[64];
    int t = threadIdx.x;
    for (int i = t; i < 64 * 32; i += blockDim.x) sW1[i] = nw1[i];
    for (int i = t; i < 32 * 32; i += blockDim.x) sW2[i] = nw2[i];
    if (NEXT) {
        for (int i = t; i < 64 * 32; i += blockDim.x) sE[i] = ew1n[i];
        if (t < 32) seb[t] = eb1n[t];
    }
    if (OUT) {
        for (int i = t; i < 32 * 64; i += blockDim.x) sE[i] = ow[i];
        if (t < 64) seb[t] = ob[t];
    }
    if (t < 32) { sb1[t] = nb1[t]; sb2[t] = nb2[t]; }
    __syncthreads();

    int n = blockIdx.x * blockDim.x + t;
    if (n >= N_NODES) return;

    float cnt = (float)max(g_hist[n], 1);
    if (OUT) {
        g_hist[n] = 0;
        if (blockIdx.x == 0 && t < NBLK_SCAN) g_flag[t] = 0;
    }
    float inv = __fdividef(1.0f, cnt);
    float2 xa = reinterpret_cast<float2*>(g_xacc)[n];
    if (!OUT) {
        float2 xv = reinterpret_cast<float2*>(g_x)[n];
        xv.x = fmaf(xa.x, inv, xv.x);
        xv.y = fmaf(xa.y, inv, xv.y);
        reinterpret_cast<float2*>(g_x)[n] = xv;
        reinterpret_cast<float2*>(g_xacc)[n] = make_float2(0.f, 0.f);
    }

    float cat[64];
    float4* hio = reinterpret_cast<float4*>(g_h + n * 32);
    float4* agp = reinterpret_cast<float4*>(g_agg + n * 32);
#pragma unroll
    for (int i = 0; i < 8; i++) {
        float4 h4 = hio[i], a4 = agp[i];
        cat[4 * i + 0] = h4.x; cat[4 * i + 1] = h4.y; cat[4 * i + 2] = h4.z; cat[4 * i + 3] = h4.w;
        cat[32 + 4 * i + 0] = a4.x; cat[32 + 4 * i + 1] = a4.y;
        cat[32 + 4 * i + 2] = a4.z; cat[32 + 4 * i + 3] = a4.w;
        agp[i] = make_float4(0.f, 0.f, 0.f, 0.f);
    }
    float u[32];
    matvec32<64, true, true>(cat, sW1, sb1, u);
    float upd[32];
    matvec32<32, false, true>(u, sW2, sb2, upd);
    float hn[32];
#pragma unroll
    for (int i = 0; i < 32; i++) hn[i] = cat[i] + upd[i];

    if (NEXT) {
        store32(g_h + n * 32, hn);
        float a[32], bb[32];
        matvec32<32, false, true >(hn, sE,           seb, a);
        matvec32<32, false, false>(hn, sE + 32 * 32, seb, bb);
        store32(g_A + n * 32, a);
        store32(g_B + n * 32, bb);
    }
    if (OUT) {
        float2 acc[32];
#pragma unroll
        for (int j = 0; j < 32; j++) acc[j] = reinterpret_cast<const float2*>(seb)[j];
#pragma unroll
        for (int i = 0; i < 32; i++) {
            float2 vv = make_float2(hn[i], hn[i]);
            const float4* wr = reinterpret_cast<const float4*>(sE + i * 64);
#pragma unroll
            for (int j = 0; j < 16; j++) {
                float4 w4 = wr[j];
                acc[2 * j]     = ffma2(vv, make_float2(w4.x, w4.y), acc[2 * j]);
                acc[2 * j + 1] = ffma2(vv, make_float2(w4.z, w4.w), acc[2 * j + 1]);
            }
        }
        float2* op = reinterpret_cast<float2*>(out + n * 64);
#pragma unroll
        for (int j = 0; j < 32; j++) op[j] = acc[j];
    }
}

// ---------------- host launcher ----------------
extern "C" void kernel_launch(void* const* d_in, const int* in_sizes, int n_in,
                              void* d_out, int out_size)
{
    const float* data      = (const float*)d_in[0];
    const float* pos       = (const float*)d_in[1];
    const float* ea        = (const float*)d_in[2];
    const float* tptr      = (const float*)d_in[3];
    const int*   row       = (const int*)d_in[4];
    const int*   col       = (const int*)d_in[5];
    const float* emb_in_w  = (const float*)d_in[6];
    const float* emb_in_b  = (const float*)d_in[7];
    const float* emb_out_w = (const float*)d_in[8];
    const float* emb_out_b = (const float*)d_in[9];
    const float* edge_w1   = (const float*)d_in[10];
    const float* edge_b1   = (const float*)d_in[11];
    const float* edge_w2   = (const float*)d_in[12];
    const float* edge_b2   = (const float*)d_in[13];
    const float* node_w1   = (const float*)d_in[14];
    const float* node_b1   = (const float*)d_in[15];
    const float* node_w2   = (const float*)d_in[16];
    const float* node_b2   = (const float*)d_in[17];
    const float* coord_w1  = (const float*)d_in[18];
    const float* coord_b1  = (const float*)d_in[19];
    const float* coord_w2  = (const float*)d_in[20];

    k_inithist<<<NB_N + NB_E, 256>>>(data, pos, tptr, emb_in_w, emb_in_b,
                                     edge_w1, edge_b1, row);
    k_scan_lb<<<NBLK_SCAN, SCAN_B>>>();
    k_scatter<<<NB_E, 256>>>(row, col, ea);

    for (int l = 0; l < NLAYERS; l++) {
        k_edge<<<EDGE_BLOCKS, 32 * WPB>>>(edge_w1 + l * 66 * 32,
                              edge_w2 + l * 1024, edge_b2 + l * 32,
                              coord_w1 + l * 1024, coord_b1 + l * 32,
                              coord_w2 + l * 32);
        if (l < NLAYERS - 1)
            k_node<true, false><<<NB_NODE, NODE_T>>>(node_w1 + l * 2048, node_b1 + l * 32,
                                        node_w2 + l * 1024, node_b2 + l * 32,
                                        edge_w1 + (l + 1) * 66 * 32, edge_b1 + (l + 1) * 32,
                                        nullptr, nullptr, nullptr);
        else
            k_node<false, true><<<NB_NODE, NODE_T>>>(node_w1 + l * 2048, node_b1 + l * 32,
                                         node_w2 + l * 1024, node_b2 + l * 32,
                                         nullptr, nullptr,
                                         emb_out_w, emb_out_b, (float*)d_out);
    }
}